// round 3
// baseline (speedup 1.0000x reference)
#include <cuda_runtime.h>
#include <math.h>

#define D_MODEL 1024
#define D_FF    2816
#define NHEADS  16
#define DK      64
#define BATCH   2
#define SEQ     2048
#define BSROWS  (BATCH*SEQ)   // 4096
#define EPSV    1e-5f

// ---------------- scratch (no cudaMalloc allowed) ----------------
static __device__ float g_h   [(size_t)BSROWS*D_MODEL];
static __device__ float g_q   [(size_t)BSROWS*D_MODEL];
static __device__ float g_k   [(size_t)BSROWS*D_MODEL];
static __device__ float g_v   [(size_t)BSROWS*D_MODEL];
static __device__ float g_attn[(size_t)BSROWS*D_MODEL];
static __device__ float g_y   [(size_t)BSROWS*D_MODEL];
static __device__ float g_u   [(size_t)BSROWS*D_FF];
static __device__ float g_g   [(size_t)BSROWS*D_FF];

// ---------------- RMSNorm: one block per row ----------------
__global__ void rmsnorm_k(const float* __restrict__ x, const float* __restrict__ gains,
                          float* __restrict__ o) {
    int row = blockIdx.x;
    const float* xr = x + (size_t)row * D_MODEL;
    float*       orow = o + (size_t)row * D_MODEL;
    float s = 0.f;
    for (int i = threadIdx.x; i < D_MODEL; i += 256) { float v = xr[i]; s += v * v; }
    #pragma unroll
    for (int off = 16; off; off >>= 1) s += __shfl_xor_sync(0xffffffffu, s, off);
    __shared__ float ws[8];
    __shared__ float rinv;
    if ((threadIdx.x & 31) == 0) ws[threadIdx.x >> 5] = s;
    __syncthreads();
    if (threadIdx.x == 0) {
        float t = 0.f;
        #pragma unroll
        for (int i = 0; i < 8; i++) t += ws[i];
        rinv = rsqrtf(t / (float)D_MODEL + EPSV);
    }
    __syncthreads();
    float r = rinv;
    for (int i = threadIdx.x; i < D_MODEL; i += 256)
        orow[i] = xr[i] * gains[i] * r;
}

// ---------------- NT GEMM: C[M,N] = A[M,K] * B[N,K]^T (+res) ----------------
// All of M, N divisible by 64; K divisible by 16. 64x64 tile, 256 threads, 4x4/thread.
__global__ __launch_bounds__(256) void gemm_nt(const float* __restrict__ A,
                                               const float* __restrict__ B,
                                               const float* __restrict__ res,
                                               float* __restrict__ C,
                                               int M, int N, int K) {
    __shared__ float As[64][17];
    __shared__ float Bs[64][17];
    const int t  = threadIdx.x;
    const int tx = t & 15, ty = t >> 4;
    const int lr = t >> 2;            // 0..63
    const int lc = (t & 3) << 2;      // 0,4,8,12
    const float* Ab = A + (size_t)(blockIdx.y * 64 + lr) * K + lc;
    const float* Bb = B + (size_t)(blockIdx.x * 64 + lr) * K + lc;
    float acc[4][4] = {};
    for (int k0 = 0; k0 < K; k0 += 16) {
        float4 a4 = *(const float4*)(Ab + k0);
        float4 b4 = *(const float4*)(Bb + k0);
        As[lr][lc+0] = a4.x; As[lr][lc+1] = a4.y; As[lr][lc+2] = a4.z; As[lr][lc+3] = a4.w;
        Bs[lr][lc+0] = b4.x; Bs[lr][lc+1] = b4.y; Bs[lr][lc+2] = b4.z; Bs[lr][lc+3] = b4.w;
        __syncthreads();
        #pragma unroll
        for (int kk = 0; kk < 16; kk++) {
            float a[4], b[4];
            #pragma unroll
            for (int i = 0; i < 4; i++) a[i] = As[ty * 4 + i][kk];
            #pragma unroll
            for (int j = 0; j < 4; j++) b[j] = Bs[tx * 4 + j][kk];
            #pragma unroll
            for (int i = 0; i < 4; i++)
                #pragma unroll
                for (int j = 0; j < 4; j++)
                    acc[i][j] += a[i] * b[j];
        }
        __syncthreads();
    }
    #pragma unroll
    for (int i = 0; i < 4; i++) {
        int r = blockIdx.y * 64 + ty * 4 + i;
        #pragma unroll
        for (int j = 0; j < 4; j++) {
            int c = blockIdx.x * 64 + tx * 4 + j;
            float vv = acc[i][j];
            if (res) vv += res[(size_t)r * N + c];
            C[(size_t)r * N + c] = vv;
        }
    }
}

// ---------------- RoPE in-place on [B,S,H,DK], interleaved pairs ----------------
__global__ void rope_k(float* __restrict__ x) {
    int idx = blockIdx.x * blockDim.x + threadIdx.x;     // over BSROWS*512 pairs
    if (idx >= BSROWS * (D_MODEL / 2)) return;
    int row  = idx >> 9;            // 512 pairs per row
    int p    = idx & 511;
    int s    = row & (SEQ - 1);
    int head = p >> 5;              // 32 pairs per head
    int j    = p & 31;
    float ex  = -(2.f * (float)j) / 64.f * logf(10000.f);
    float inv = expf(ex);
    float ang = (float)s * inv;
    float sn, cs; sincosf(ang, &sn, &cs);
    size_t base = (size_t)row * D_MODEL + head * 64 + 2 * j;
    float x0 = x[base], x1 = x[base + 1];
    x[base]     = x0 * cs - x1 * sn;
    x[base + 1] = x1 * cs + x0 * sn;
}

// ---------------- Flash attention (fp32, causal) ----------------
// grid: (SEQ/64, BATCH*NHEADS), block 256. Q tile 64 rows; iterate 64-key tiles.
// Thread layout: row = t>>2 (0..63), c4 = t&3; each thread owns 16 score cols and
// 16 output dims (d0 = c4*16).
#define ATTN_SMEM (4 * 64 * 65 * 4)
__global__ __launch_bounds__(256) void attn_k(const float* __restrict__ q,
                                              const float* __restrict__ k,
                                              const float* __restrict__ v,
                                              float* __restrict__ o) {
    extern __shared__ float sm[];
    float* Qs = sm;
    float* Ks = Qs + 64 * 65;
    float* Vs = Ks + 64 * 65;
    float* Ps = Vs + 64 * 65;
    const int bh = blockIdx.y;
    const int b  = bh / NHEADS, h = bh % NHEADS;
    const int q0 = blockIdx.x * 64;
    const int t  = threadIdx.x;
    const int row = t >> 2;
    const int c4  = t & 3;
    const int d0  = c4 * 16;
    const int kcb = c4 * 16;

    // load Q tile
    for (int i = t; i < 64 * 64; i += 256) {
        int r = i >> 6, d = i & 63;
        Qs[r * 65 + d] = q[((size_t)(b * SEQ + q0 + r)) * D_MODEL + h * 64 + d];
    }
    __syncthreads();

    float acc[16];
    #pragma unroll
    for (int i = 0; i < 16; i++) acc[i] = 0.f;
    float m = -1e30f, l = 0.f;
    const float scale = 0.125f;  // 1/sqrt(64)

    for (int k0 = 0; k0 <= q0; k0 += 64) {
        // load K,V tiles
        for (int i = t; i < 64 * 64; i += 256) {
            int r = i >> 6, d = i & 63;
            size_t gi = ((size_t)(b * SEQ + k0 + r)) * D_MODEL + h * 64 + d;
            Ks[r * 65 + d] = k[gi];
            Vs[r * 65 + d] = v[gi];
        }
        __syncthreads();

        // scores for 16 key columns
        float s[16];
        #pragma unroll
        for (int jj = 0; jj < 16; jj++) {
            float dot = 0.f;
            #pragma unroll 8
            for (int d = 0; d < 64; d++)
                dot += Qs[row * 65 + d] * Ks[(kcb + jj) * 65 + d];
            float sc = dot * scale;
            if (k0 + kcb + jj > q0 + row) sc = -1e30f;
            s[jj] = sc;
        }
        // row max across this thread + the 4 lanes sharing the row
        float mloc = s[0];
        #pragma unroll
        for (int jj = 1; jj < 16; jj++) mloc = fmaxf(mloc, s[jj]);
        mloc = fmaxf(mloc, __shfl_xor_sync(0xffffffffu, mloc, 1));
        mloc = fmaxf(mloc, __shfl_xor_sync(0xffffffffu, mloc, 2));
        float mnew = fmaxf(m, mloc);
        float corr = __expf(m - mnew);
        float psum = 0.f;
        #pragma unroll
        for (int jj = 0; jj < 16; jj++) {
            float p = __expf(s[jj] - mnew);
            Ps[row * 65 + kcb + jj] = p;
            psum += p;
        }
        psum += __shfl_xor_sync(0xffffffffu, psum, 1);
        psum += __shfl_xor_sync(0xffffffffu, psum, 2);
        l = l * corr + psum;
        m = mnew;
        #pragma unroll
        for (int i = 0; i < 16; i++) acc[i] *= corr;
        __syncwarp();   // Ps row written entirely within this warp
        // PV accumulate over this thread's 16 output dims
        for (int kc = 0; kc < 64; kc++) {
            float p = Ps[row * 65 + kc];
            #pragma unroll
            for (int dd = 0; dd < 16; dd++)
                acc[dd] += p * Vs[kc * 65 + d0 + dd];
        }
        __syncthreads();  // before K/V tile reload
    }

    float invl = 1.f / l;
    size_t obase = ((size_t)(b * SEQ + q0 + row)) * D_MODEL + h * 64 + d0;
    #pragma unroll
    for (int dd = 0; dd < 16; dd++) o[obase + dd] = acc[dd] * invl;
}

// ---------------- SwiGLU elementwise: u <- u*sigmoid(u)*g ----------------
__global__ void swiglu_k(float* __restrict__ u, const float* __restrict__ g) {
    size_t i = (size_t)blockIdx.x * blockDim.x + threadIdx.x;
    if (i < (size_t)BSROWS * D_FF) {
        float uv = u[i];
        float sg = 1.f / (1.f + __expf(-uv));
        u[i] = uv * sg * g[i];
    }
}

// ---------------- launch ----------------
extern "C" void kernel_launch(void* const* d_in, const int* in_sizes, int n_in,
                              void* d_out, int out_size) {
    const float* x      = (const float*)d_in[0];
    const float* gains1 = (const float*)d_in[1];
    const float* gains2 = (const float*)d_in[2];
    const float* WQ     = (const float*)d_in[3];
    const float* WK     = (const float*)d_in[4];
    const float* WV     = (const float*)d_in[5];
    const float* WO     = (const float*)d_in[6];
    const float* W1     = (const float*)d_in[7];
    const float* W2     = (const float*)d_in[8];
    const float* W3     = (const float*)d_in[9];
    float* out = (float*)d_out;

    float *h, *q, *k, *v, *attn, *y, *u, *g;
    cudaGetSymbolAddress((void**)&h,    g_h);
    cudaGetSymbolAddress((void**)&q,    g_q);
    cudaGetSymbolAddress((void**)&k,    g_k);
    cudaGetSymbolAddress((void**)&v,    g_v);
    cudaGetSymbolAddress((void**)&attn, g_attn);
    cudaGetSymbolAddress((void**)&y,    g_y);
    cudaGetSymbolAddress((void**)&u,    g_u);
    cudaGetSymbolAddress((void**)&g,    g_g);

    // 1. pre-attention RMSNorm
    rmsnorm_k<<<BSROWS, 256>>>(x, gains1, h);

    // 2. QKV projections
    dim3 gqkv(D_MODEL / 64, BSROWS / 64);
    gemm_nt<<<gqkv, 256>>>(h, WQ, nullptr, q, BSROWS, D_MODEL, D_MODEL);
    gemm_nt<<<gqkv, 256>>>(h, WK, nullptr, k, BSROWS, D_MODEL, D_MODEL);
    gemm_nt<<<gqkv, 256>>>(h, WV, nullptr, v, BSROWS, D_MODEL, D_MODEL);

    // 3. RoPE on q, k
    int ropeN = BSROWS * (D_MODEL / 2);
    rope_k<<<(ropeN + 255) / 256, 256>>>(q);
    rope_k<<<(ropeN + 255) / 256, 256>>>(k);

    // 4. causal flash attention
    cudaFuncSetAttribute(attn_k, cudaFuncAttributeMaxDynamicSharedMemorySize, ATTN_SMEM);
    attn_k<<<dim3(SEQ / 64, BATCH * NHEADS), 256, ATTN_SMEM>>>(q, k, v, attn);

    // 5. output projection + residual
    gemm_nt<<<gqkv, 256>>>(attn, WO, x, y, BSROWS, D_MODEL, D_MODEL);

    // 6. pre-FFN RMSNorm
    rmsnorm_k<<<BSROWS, 256>>>(y, gains2, h);

    // 7. FFN up/gate
    dim3 gff(D_FF / 64, BSROWS / 64);
    gemm_nt<<<gff, 256>>>(h, W1, nullptr, u, BSROWS, D_FF, D_MODEL);
    gemm_nt<<<gff, 256>>>(h, W3, nullptr, g, BSROWS, D_FF, D_MODEL);

    // 8. SwiGLU
    size_t nsw = (size_t)BSROWS * D_FF;
    swiglu_k<<<(int)((nsw + 255) / 256), 256>>>(u, g);

    // 9. down projection + residual -> out
    gemm_nt<<<gqkv, 256>>>(u, W2, y, out, BSROWS, D_MODEL, D_FF);
}

// round 4
// speedup vs baseline: 1.0036x; 1.0036x over previous
#include <cuda_runtime.h>
#include <math.h>

#define D_MODEL 1024
#define D_FF    2816
#define NHEADS  16
#define DK      64
#define BATCH   2
#define SEQ     2048
#define BSROWS  (BATCH*SEQ)   // 4096
#define EPSV    1e-5f

// ---------------- scratch (no cudaMalloc allowed) ----------------
static __device__ float g_h   [(size_t)BSROWS*D_MODEL];
static __device__ float g_q   [(size_t)BSROWS*D_MODEL];
static __device__ float g_k   [(size_t)BSROWS*D_MODEL];
static __device__ float g_v   [(size_t)BSROWS*D_MODEL];
static __device__ float g_attn[(size_t)BSROWS*D_MODEL];
static __device__ float g_y   [(size_t)BSROWS*D_MODEL];
static __device__ float g_u   [(size_t)BSROWS*D_FF];
static __device__ float g_g   [(size_t)BSROWS*D_FF];

// ---------------- RMSNorm: one block per row ----------------
__global__ void rmsnorm_k(const float* __restrict__ x, const float* __restrict__ gains,
                          float* __restrict__ o) {
    int row = blockIdx.x;
    const float* xr = x + (size_t)row * D_MODEL;
    float*       orow = o + (size_t)row * D_MODEL;
    float s = 0.f;
    for (int i = threadIdx.x; i < D_MODEL; i += 256) { float v = xr[i]; s += v * v; }
    #pragma unroll
    for (int off = 16; off; off >>= 1) s += __shfl_xor_sync(0xffffffffu, s, off);
    __shared__ float ws[8];
    __shared__ float rinv;
    if ((threadIdx.x & 31) == 0) ws[threadIdx.x >> 5] = s;
    __syncthreads();
    if (threadIdx.x == 0) {
        float t = 0.f;
        #pragma unroll
        for (int i = 0; i < 8; i++) t += ws[i];
        rinv = rsqrtf(t / (float)D_MODEL + EPSV);
    }
    __syncthreads();
    float r = rinv;
    for (int i = threadIdx.x; i < D_MODEL; i += 256)
        orow[i] = xr[i] * gains[i] * r;
}

// ---------------- NT GEMM: C[M,N] = A[M,K] * B[N,K]^T (+res) ----------------
// All of M, N divisible by 64; K divisible by 16. 64x64 tile, 256 threads, 4x4/thread.
__global__ __launch_bounds__(256) void gemm_nt(const float* __restrict__ A,
                                               const float* __restrict__ B,
                                               const float* __restrict__ res,
                                               float* __restrict__ C,
                                               int M, int N, int K) {
    __shared__ float As[64][17];
    __shared__ float Bs[64][17];
    const int t  = threadIdx.x;
    const int tx = t & 15, ty = t >> 4;
    const int lr = t >> 2;            // 0..63
    const int lc = (t & 3) << 2;      // 0,4,8,12
    const float* Ab = A + (size_t)(blockIdx.y * 64 + lr) * K + lc;
    const float* Bb = B + (size_t)(blockIdx.x * 64 + lr) * K + lc;
    float acc[4][4] = {};
    for (int k0 = 0; k0 < K; k0 += 16) {
        float4 a4 = *(const float4*)(Ab + k0);
        float4 b4 = *(const float4*)(Bb + k0);
        As[lr][lc+0] = a4.x; As[lr][lc+1] = a4.y; As[lr][lc+2] = a4.z; As[lr][lc+3] = a4.w;
        Bs[lr][lc+0] = b4.x; Bs[lr][lc+1] = b4.y; Bs[lr][lc+2] = b4.z; Bs[lr][lc+3] = b4.w;
        __syncthreads();
        #pragma unroll
        for (int kk = 0; kk < 16; kk++) {
            float a[4], b[4];
            #pragma unroll
            for (int i = 0; i < 4; i++) a[i] = As[ty * 4 + i][kk];
            #pragma unroll
            for (int j = 0; j < 4; j++) b[j] = Bs[tx * 4 + j][kk];
            #pragma unroll
            for (int i = 0; i < 4; i++)
                #pragma unroll
                for (int j = 0; j < 4; j++)
                    acc[i][j] += a[i] * b[j];
        }
        __syncthreads();
    }
    #pragma unroll
    for (int i = 0; i < 4; i++) {
        int r = blockIdx.y * 64 + ty * 4 + i;
        #pragma unroll
        for (int j = 0; j < 4; j++) {
            int c = blockIdx.x * 64 + tx * 4 + j;
            float vv = acc[i][j];
            if (res) vv += res[(size_t)r * N + c];
            C[(size_t)r * N + c] = vv;
        }
    }
}

// ---------------- RoPE in-place on [B,S,H,DK], interleaved pairs ----------------
__global__ void rope_k(float* __restrict__ x) {
    int idx = blockIdx.x * blockDim.x + threadIdx.x;     // over BSROWS*512 pairs
    if (idx >= BSROWS * (D_MODEL / 2)) return;
    int row  = idx >> 9;            // 512 pairs per row
    int p    = idx & 511;
    int s    = row & (SEQ - 1);
    int head = p >> 5;              // 32 pairs per head
    int j    = p & 31;
    float ex  = -(2.f * (float)j) / 64.f * logf(10000.f);
    float inv = expf(ex);
    float ang = (float)s * inv;
    float sn, cs; sincosf(ang, &sn, &cs);
    size_t base = (size_t)row * D_MODEL + head * 64 + 2 * j;
    float x0 = x[base], x1 = x[base + 1];
    x[base]     = x0 * cs - x1 * sn;
    x[base + 1] = x1 * cs + x0 * sn;
}

// ---------------- Flash attention (fp32, causal) ----------------
// grid: (SEQ/64, BATCH*NHEADS), block 256. Q tile 64 rows; iterate 64-key tiles.
// Thread layout: row = t>>2 (0..63), c4 = t&3; each thread owns 16 score cols and
// 16 output dims (d0 = c4*16).
#define ATTN_SMEM (4 * 64 * 65 * 4)
__global__ __launch_bounds__(256) void attn_k(const float* __restrict__ q,
                                              const float* __restrict__ k,
                                              const float* __restrict__ v,
                                              float* __restrict__ o) {
    extern __shared__ float sm[];
    float* Qs = sm;
    float* Ks = Qs + 64 * 65;
    float* Vs = Ks + 64 * 65;
    float* Ps = Vs + 64 * 65;
    const int bh = blockIdx.y;
    const int b  = bh / NHEADS, h = bh % NHEADS;
    const int q0 = blockIdx.x * 64;
    const int t  = threadIdx.x;
    const int row = t >> 2;
    const int c4  = t & 3;
    const int d0  = c4 * 16;
    const int kcb = c4 * 16;

    // load Q tile
    for (int i = t; i < 64 * 64; i += 256) {
        int r = i >> 6, d = i & 63;
        Qs[r * 65 + d] = q[((size_t)(b * SEQ + q0 + r)) * D_MODEL + h * 64 + d];
    }
    __syncthreads();

    float acc[16];
    #pragma unroll
    for (int i = 0; i < 16; i++) acc[i] = 0.f;
    float m = -1e30f, l = 0.f;
    const float scale = 0.125f;  // 1/sqrt(64)

    for (int k0 = 0; k0 <= q0; k0 += 64) {
        // load K,V tiles
        for (int i = t; i < 64 * 64; i += 256) {
            int r = i >> 6, d = i & 63;
            size_t gi = ((size_t)(b * SEQ + k0 + r)) * D_MODEL + h * 64 + d;
            Ks[r * 65 + d] = k[gi];
            Vs[r * 65 + d] = v[gi];
        }
        __syncthreads();

        // scores for 16 key columns
        float s[16];
        #pragma unroll
        for (int jj = 0; jj < 16; jj++) {
            float dot = 0.f;
            #pragma unroll 8
            for (int d = 0; d < 64; d++)
                dot += Qs[row * 65 + d] * Ks[(kcb + jj) * 65 + d];
            float sc = dot * scale;
            if (k0 + kcb + jj > q0 + row) sc = -1e30f;
            s[jj] = sc;
        }
        // row max across this thread + the 4 lanes sharing the row
        float mloc = s[0];
        #pragma unroll
        for (int jj = 1; jj < 16; jj++) mloc = fmaxf(mloc, s[jj]);
        mloc = fmaxf(mloc, __shfl_xor_sync(0xffffffffu, mloc, 1));
        mloc = fmaxf(mloc, __shfl_xor_sync(0xffffffffu, mloc, 2));
        float mnew = fmaxf(m, mloc);
        float corr = __expf(m - mnew);
        float psum = 0.f;
        #pragma unroll
        for (int jj = 0; jj < 16; jj++) {
            float p = __expf(s[jj] - mnew);
            Ps[row * 65 + kcb + jj] = p;
            psum += p;
        }
        psum += __shfl_xor_sync(0xffffffffu, psum, 1);
        psum += __shfl_xor_sync(0xffffffffu, psum, 2);
        l = l * corr + psum;
        m = mnew;
        #pragma unroll
        for (int i = 0; i < 16; i++) acc[i] *= corr;
        __syncwarp();   // Ps row written entirely within this warp
        // PV accumulate over this thread's 16 output dims
        for (int kc = 0; kc < 64; kc++) {
            float p = Ps[row * 65 + kc];
            #pragma unroll
            for (int dd = 0; dd < 16; dd++)
                acc[dd] += p * Vs[kc * 65 + d0 + dd];
        }
        __syncthreads();  // before K/V tile reload
    }

    float invl = 1.f / l;
    size_t obase = ((size_t)(b * SEQ + q0 + row)) * D_MODEL + h * 64 + d0;
    #pragma unroll
    for (int dd = 0; dd < 16; dd++) o[obase + dd] = acc[dd] * invl;
}

// ---------------- SwiGLU elementwise: u <- u*sigmoid(u)*g ----------------
__global__ void swiglu_k(float* __restrict__ u, const float* __restrict__ g) {
    size_t i = (size_t)blockIdx.x * blockDim.x + threadIdx.x;
    if (i < (size_t)BSROWS * D_FF) {
        float uv = u[i];
        float sg = 1.f / (1.f + __expf(-uv));
        u[i] = uv * sg * g[i];
    }
}

// ---------------- launch ----------------
extern "C" void kernel_launch(void* const* d_in, const int* in_sizes, int n_in,
                              void* d_out, int out_size) {
    const float* x      = (const float*)d_in[0];
    const float* gains1 = (const float*)d_in[1];
    const float* gains2 = (const float*)d_in[2];
    const float* WQ     = (const float*)d_in[3];
    const float* WK     = (const float*)d_in[4];
    const float* WV     = (const float*)d_in[5];
    const float* WO     = (const float*)d_in[6];
    const float* W1     = (const float*)d_in[7];
    const float* W2     = (const float*)d_in[8];
    const float* W3     = (const float*)d_in[9];
    float* out = (float*)d_out;

    float *h, *q, *k, *v, *attn, *y, *u, *g;
    cudaGetSymbolAddress((void**)&h,    g_h);
    cudaGetSymbolAddress((void**)&q,    g_q);
    cudaGetSymbolAddress((void**)&k,    g_k);
    cudaGetSymbolAddress((void**)&v,    g_v);
    cudaGetSymbolAddress((void**)&attn, g_attn);
    cudaGetSymbolAddress((void**)&y,    g_y);
    cudaGetSymbolAddress((void**)&u,    g_u);
    cudaGetSymbolAddress((void**)&g,    g_g);

    // 1. pre-attention RMSNorm
    rmsnorm_k<<<BSROWS, 256>>>(x, gains1, h);

    // 2. QKV projections
    dim3 gqkv(D_MODEL / 64, BSROWS / 64);
    gemm_nt<<<gqkv, 256>>>(h, WQ, nullptr, q, BSROWS, D_MODEL, D_MODEL);
    gemm_nt<<<gqkv, 256>>>(h, WK, nullptr, k, BSROWS, D_MODEL, D_MODEL);
    gemm_nt<<<gqkv, 256>>>(h, WV, nullptr, v, BSROWS, D_MODEL, D_MODEL);

    // 3. RoPE on q, k
    int ropeN = BSROWS * (D_MODEL / 2);
    rope_k<<<(ropeN + 255) / 256, 256>>>(q);
    rope_k<<<(ropeN + 255) / 256, 256>>>(k);

    // 4. causal flash attention
    cudaFuncSetAttribute(attn_k, cudaFuncAttributeMaxDynamicSharedMemorySize, ATTN_SMEM);
    attn_k<<<dim3(SEQ / 64, BATCH * NHEADS), 256, ATTN_SMEM>>>(q, k, v, attn);

    // 5. output projection + residual
    gemm_nt<<<gqkv, 256>>>(attn, WO, x, y, BSROWS, D_MODEL, D_MODEL);

    // 6. pre-FFN RMSNorm
    rmsnorm_k<<<BSROWS, 256>>>(y, gains2, h);

    // 7. FFN up/gate
    dim3 gff(D_FF / 64, BSROWS / 64);
    gemm_nt<<<gff, 256>>>(h, W1, nullptr, u, BSROWS, D_FF, D_MODEL);
    gemm_nt<<<gff, 256>>>(h, W3, nullptr, g, BSROWS, D_FF, D_MODEL);

    // 8. SwiGLU
    size_t nsw = (size_t)BSROWS * D_FF;
    swiglu_k<<<(int)((nsw + 255) / 256), 256>>>(u, g);

    // 9. down projection + residual -> out
    gemm_nt<<<gqkv, 256>>>(u, W2, y, out, BSROWS, D_MODEL, D_FF);
}